// round 12
// baseline (speedup 1.0000x reference)
#include <cuda_runtime.h>
#include <cuda_bf16.h>
#include <cstdint>

#define NATOMS 50000
#define INDIM  128
#define HID    256
#define NELEM  4
#define NIMG   500
#define NNZV   2000000
#define NPAD   50560            // 395 * 128 >= NATOMS + 4*127
#define NT128  (NPAD / 128)     // 395
#define OUTSZ  (NIMG + 3 * NATOMS)

// ---------------- device scratch (referenced ONLY in device code) ----------
__device__ float d_H0[(size_t)NPAD * HID];
__device__ float d_D1[(size_t)NPAD * HID];
__device__ float d_G[(size_t)NATOMS * INDIM];
__device__ float d_rowE[NPAD];
__device__ float d_W0T[NELEM * HID * INDIM]; // [e][h][d]
__device__ float d_W1T[NELEM * HID * HID];   // [e][j][i]
__device__ int   d_perm[NPAD];
__device__ int   d_cnt[NELEM];
__device__ int   d_cur[NELEM];
__device__ int   d_off[NELEM + 1];
__device__ int   d_is64[2];

__device__ const int*   dp_an;
__device__ const int*   dp_img;
__device__ const int*   dp_rows;
__device__ const int*   dp_cols;
__device__ const float* dp_vals;
__device__ const float* dp_b0;
__device__ const float* dp_b1;
__device__ const float* dp_w2;

__device__ __forceinline__ int ld_idx(const int* __restrict__ p, int i, int is64) {
    return p[is64 ? (2 * i) : i];
}
__device__ __forceinline__ int emap(int z) {
    return z == 1 ? 0 : (z == 6 ? 1 : (z == 8 ? 2 : 3));
}
__device__ __forceinline__ bool in_elem_set(int v) {
    return v == 1 || v == 6 || v == 8 || v == 29;
}
__device__ __forceinline__ unsigned bpack(float x, float y) {
    __nv_bfloat162 t = __floats2bfloat162_rn(x, y);
    return *reinterpret_cast<unsigned*>(&t);
}
__device__ __forceinline__ void split_pair(float x, float y,
                                           unsigned& hi, unsigned& lo) {
    float hx = __bfloat162float(__float2bfloat16(x));
    float hy = __bfloat162float(__float2bfloat16(y));
    hi = bpack(hx, hy);
    lo = bpack(x - hx, y - hy);
}
__device__ __forceinline__ void mma16(float* c, const unsigned* a,
                                      unsigned b0, unsigned b1) {
    asm volatile(
        "mma.sync.aligned.m16n8k16.row.col.f32.bf16.bf16.f32 "
        "{%0,%1,%2,%3}, {%4,%5,%6,%7}, {%8,%9}, {%0,%1,%2,%3};"
        : "+f"(c[0]), "+f"(c[1]), "+f"(c[2]), "+f"(c[3])
        : "r"(a[0]), "r"(a[1]), "r"(a[2]), "r"(a[3]), "r"(b0), "r"(b1));
}

// persistent-activation smem layout (165,376 B)
struct SmemT {
    unsigned Ahi[128][132];  // activation buffer (H0 in fwd, D0 in bwd), bf16x2 hi
    unsigned Alo[128][132];  //   ... lo
    unsigned Fhi[128][20];   // per-chunk fill buffer for global-A phases
    unsigned Flo[128][20];
    unsigned Bhi[8][136];    // per-chunk B tile
    unsigned Blo[8][136];
    int      perm[128];
    float    srow[128];
};
#define SMT_BYTES ((int)sizeof(SmemT))

// ---------------- input identification (+ counter reset) ----------------
__global__ void k_detect(const int* pa, const int* pb,
                         const int* q0, const int* q1, const int* q2,
                         const float* r0, const float* r1, const float* r2) {
    __shared__ int s_anfail[2];
    __shared__ int s_isf[3];
    __shared__ int s_qmax[3];
    __shared__ int s_bmax[3];
    int tid = threadIdx.x;
    if (tid < 2) s_anfail[tid] = 0;
    if (tid < 3) { s_isf[tid] = 0; s_qmax[tid] = 0; s_bmax[tid] = 0; }
    if (tid < NELEM) { d_cnt[tid] = 0; d_cur[tid] = 0; }
    __syncthreads();

    const int* pp[2] = {pa, pb};
    const int* qq[3] = {q0, q1, q2};
    const float* rr[3] = {r0, r1, r2};

    if (tid < 32) {
        int c = tid >> 4;
        int i = tid & 15;
        if (!in_elem_set(pp[c][2 * i])) atomicExch(&s_anfail[c], 1);
    }
    for (int j = 0; j < 3; j++) {
        const int* q = qq[j];
        for (int i = tid; i < 1024; i += blockDim.x) {
            int w = q[i];
            if (w < 0 || w > 0x30000000) atomicExch(&s_isf[j], 1);
            atomicMax(&s_qmax[j], w);
        }
    }
    for (int j = 0; j < 3; j++) {
        const float* r = rr[j];
        for (int i = tid; i < 1024; i += blockDim.x) {
            float v = fabsf(r[i]);
            atomicMax(&s_bmax[j], __float_as_int(v));
        }
    }
    __syncthreads();

    if (tid == 0) {
        int asel = s_anfail[0] ? (s_anfail[1] ? 0 : 1) : 0;
        dp_an  = pp[asel];
        dp_img = pp[1 - asel];
        d_is64[0] = (pp[asel][1] == 0 && pp[asel][3] == 0 && pp[asel][5] == 0) ? 1 : 0;

        int vsel = 2;
        if (s_isf[0]) vsel = 0; else if (s_isf[1]) vsel = 1; else if (s_isf[2]) vsel = 2;
        int o1 = (vsel == 0) ? 1 : 0;
        int o2 = (vsel == 2) ? 1 : 2;
        int rsel = (s_qmax[o1] >= s_qmax[o2]) ? o1 : o2;
        int csel = o1 + o2 - rsel;
        dp_vals = (const float*)qq[vsel];
        dp_rows = qq[rsel];
        dp_cols = qq[csel];
        const int* rw = qq[rsel];
        d_is64[1] = (rw[1] == 0 && rw[3] == 0 && rw[5] == 0 && rw[7] == 0 &&
                     rw[9] == 0 && rw[11] == 0) ? 1 : 0;

        int b0s;
        if (s_bmax[0] >= s_bmax[1] && s_bmax[0] >= s_bmax[2]) b0s = 0;
        else if (s_bmax[1] >= s_bmax[2]) b0s = 1;
        else b0s = 2;
        int b1s = (b0s + 1) % 3;
        int w2s = (b0s + 2) % 3;
        dp_b0 = rr[b0s]; dp_b1 = rr[b1s]; dp_w2 = rr[w2s];
    }
}

__global__ void k_zero_init(float* out) {
    int i = blockIdx.x * blockDim.x + threadIdx.x;
    if (i < OUTSZ) out[i] = 0.f;
    if (i < NPAD) { d_perm[i] = -1; d_rowE[i] = 0.f; }
}

__global__ void k_count() {
    __shared__ int sc[NELEM];
    int tid = threadIdx.x;
    if (tid < NELEM) sc[tid] = 0;
    __syncthreads();
    int i = blockIdx.x * blockDim.x + tid;
    if (i < NATOMS) atomicAdd(&sc[emap(ld_idx(dp_an, i, d_is64[0]))], 1);
    __syncthreads();
    if (tid < NELEM && sc[tid] > 0) atomicAdd(&d_cnt[tid], sc[tid]);
}

__global__ void k_scatter() {
    __shared__ int lc[NELEM], base[NELEM], loff[NELEM];
    int tid = threadIdx.x;
    if (tid < NELEM) lc[tid] = 0;
    __syncthreads();
    if (tid == 0) {
        int o = 0;
        for (int e2 = 0; e2 < NELEM; e2++) {
            loff[e2] = o;
            o += ((d_cnt[e2] + 127) / 128) * 128;
        }
        if (blockIdx.x == 0) {
            for (int e2 = 0; e2 < NELEM; e2++) d_off[e2] = loff[e2];
            d_off[NELEM] = o;
        }
    }
    __syncthreads();
    int i = blockIdx.x * blockDim.x + tid;
    int e = -1, rank = 0;
    if (i < NATOMS) {
        e = emap(ld_idx(dp_an, i, d_is64[0]));
        rank = atomicAdd(&lc[e], 1);
    }
    __syncthreads();
    if (tid < NELEM && lc[tid] > 0) base[tid] = atomicAdd(&d_cur[tid], lc[tid]);
    __syncthreads();
    if (i < NATOMS) d_perm[loff[e] + base[e] + rank] = i;
}

__global__ void k_transpose(const float* __restrict__ W0,
                            const float* __restrict__ W1) {
    const int n0 = NELEM * HID * INDIM;
    const int n1 = NELEM * HID * HID;
    int i = blockIdx.x * blockDim.x + threadIdx.x;
    if (i < n0) {
        int d = i % INDIM;
        int t = i / INDIM;
        int h = t % HID;
        int e = t / HID;
        d_W0T[i] = W0[((size_t)e * INDIM + d) * HID + h];
    } else if (i < n0 + n1) {
        int k = i - n0;
        int i2 = k % HID;
        int t = k / HID;
        int j = t % HID;
        int e = t / HID;
        d_W1T[k] = W1[((size_t)e * HID + i2) * HID + j];
    }
}

// ======================= fused FORWARD (L0+L1+layer2) =======================
__global__ __launch_bounds__(256)
void k_fwd(const float* __restrict__ FP, const float* __restrict__ W0,
           const float* __restrict__ W1) {
    extern __shared__ char smraw[];
    SmemT* sm = reinterpret_cast<SmemT*>(smraw);

    const int row0 = blockIdx.x * 128;
    if (row0 >= d_off[NELEM]) return;
    int e = 0;
#pragma unroll
    for (int t = 0; t < NELEM - 1; t++)
        if (row0 >= d_off[t + 1]) e = t + 1;

    const int tid = threadIdx.x, lane = tid & 31, wid = tid >> 5;
    const int wm = wid & 3, wn = wid >> 2;

    if (tid < 128) { sm->perm[tid] = d_perm[row0 + tid]; sm->srow[tid] = 0.f; }
    __syncthreads();

    const int frow = tid >> 1, fhalf = tid & 1;
    const int g = sm->perm[frow];
    const bool avalid = (g >= 0);
    const float* asrc = FP + (size_t)(avalid ? g : 0) * INDIM + fhalf * 8;
    const float* W0e = W0 + (size_t)e * INDIM * HID;
    const float* W1e = W1 + (size_t)e * HID * HID;
    const float4 f40 = make_float4(0.f, 0.f, 0.f, 0.f);

    // ---------------- phase A: H0 = tanh(FP@W0 + b0), both col halves -------
    for (int nc2 = 0; nc2 < 2; nc2++) {
        const int ncol0 = nc2 * 128;
        float acc[2][8][4];
#pragma unroll
        for (int mt = 0; mt < 2; mt++)
#pragma unroll
            for (int nt = 0; nt < 8; nt++)
#pragma unroll
                for (int j = 0; j < 4; j++) acc[mt][nt][j] = 0.f;

        float4 avA[2];
        float bxv[4], byv[4];
        avA[0] = avalid ? *(const float4*)(asrc)     : f40;
        avA[1] = avalid ? *(const float4*)(asrc + 4) : f40;
#pragma unroll
        for (int t = 0; t < 4; t++) {
            int idx = tid + t * 256, kp = idx >> 7, n = idx & 127;
            const float* s = W0e + (size_t)(2 * kp) * HID + ncol0 + n;
            bxv[t] = s[0]; byv[t] = s[HID];
        }

        for (int k0 = 0; k0 < INDIM; k0 += 16) {
            __syncthreads();
            {
                const int kpb = fhalf * 4;
                split_pair(avA[0].x, avA[0].y, sm->Fhi[frow][kpb],     sm->Flo[frow][kpb]);
                split_pair(avA[0].z, avA[0].w, sm->Fhi[frow][kpb + 1], sm->Flo[frow][kpb + 1]);
                split_pair(avA[1].x, avA[1].y, sm->Fhi[frow][kpb + 2], sm->Flo[frow][kpb + 2]);
                split_pair(avA[1].z, avA[1].w, sm->Fhi[frow][kpb + 3], sm->Flo[frow][kpb + 3]);
            }
#pragma unroll
            for (int t = 0; t < 4; t++) {
                int idx = tid + t * 256, kp = idx >> 7, n = idx & 127;
                split_pair(bxv[t], byv[t], sm->Bhi[kp][n], sm->Blo[kp][n]);
            }
            __syncthreads();
            if (k0 + 16 < INDIM) {
                const float* s2 = asrc + k0 + 16;
                avA[0] = avalid ? *(const float4*)(s2)     : f40;
                avA[1] = avalid ? *(const float4*)(s2 + 4) : f40;
#pragma unroll
                for (int t = 0; t < 4; t++) {
                    int idx = tid + t * 256, kp = idx >> 7, n = idx & 127;
                    const float* s = W0e + (size_t)(k0 + 16 + 2 * kp) * HID + ncol0 + n;
                    bxv[t] = s[0]; byv[t] = s[HID];
                }
            }
            unsigned ah[2][4], al[2][4];
            const int kp = lane & 3;
#pragma unroll
            for (int mt = 0; mt < 2; mt++) {
                int m = wm * 32 + mt * 16 + (lane >> 2);
                ah[mt][0] = sm->Fhi[m][kp];     ah[mt][1] = sm->Fhi[m + 8][kp];
                ah[mt][2] = sm->Fhi[m][kp + 4]; ah[mt][3] = sm->Fhi[m + 8][kp + 4];
                al[mt][0] = sm->Flo[m][kp];     al[mt][1] = sm->Flo[m + 8][kp];
                al[mt][2] = sm->Flo[m][kp + 4]; al[mt][3] = sm->Flo[m + 8][kp + 4];
            }
#pragma unroll
            for (int nt = 0; nt < 8; nt++) {
                int n = wn * 64 + nt * 8 + (lane >> 2);
                unsigned bh0 = sm->Bhi[kp][n], bh1 = sm->Bhi[kp + 4][n];
                unsigned bl0 = sm->Blo[kp][n], bl1 = sm->Blo[kp + 4][n];
#pragma unroll
                for (int mt = 0; mt < 2; mt++) {
                    mma16(acc[mt][nt], ah[mt], bh0, bh1);
                    mma16(acc[mt][nt], ah[mt], bl0, bl1);
                    mma16(acc[mt][nt], al[mt], bh0, bh1);
                }
            }
        }
        // epilogue A: tanh -> d_H0 global + persistent smem (pre-split)
#pragma unroll
        for (int mt = 0; mt < 2; mt++) {
#pragma unroll
            for (int nt = 0; nt < 8; nt++) {
                float* cc = acc[mt][nt];
                int rloc = wm * 32 + mt * 16 + (lane >> 2);
                int gc = ncol0 + wn * 64 + nt * 8 + (lane & 3) * 2;
                float2 b = *(const float2*)&dp_b0[e * HID + gc];
                float h0 = tanhf(cc[0] + b.x);
                float h1 = tanhf(cc[1] + b.y);
                float h2 = tanhf(cc[2] + b.x);
                float h3 = tanhf(cc[3] + b.y);
                size_t r0i = (size_t)(row0 + rloc) * HID + gc;
                size_t r1i = (size_t)(row0 + rloc + 8) * HID + gc;
                d_H0[r0i] = h0; d_H0[r0i + 1] = h1;
                d_H0[r1i] = h2; d_H0[r1i + 1] = h3;
                int kq = gc >> 1;
                split_pair(h0, h1, sm->Ahi[rloc][kq],     sm->Alo[rloc][kq]);
                split_pair(h2, h3, sm->Ahi[rloc + 8][kq], sm->Alo[rloc + 8][kq]);
            }
        }
    }
    __syncthreads();   // H0 smem complete

    // ---------------- phase B: H1/D1/rowE, A from smem ----------------------
    float erow[2][2] = {{0.f, 0.f}, {0.f, 0.f}};
    for (int nc2 = 0; nc2 < 2; nc2++) {
        const int ncol0 = nc2 * 128;
        float acc[2][8][4];
#pragma unroll
        for (int mt = 0; mt < 2; mt++)
#pragma unroll
            for (int nt = 0; nt < 8; nt++)
#pragma unroll
                for (int j = 0; j < 4; j++) acc[mt][nt][j] = 0.f;

        float bxv[4], byv[4];
#pragma unroll
        for (int t = 0; t < 4; t++) {
            int idx = tid + t * 256, kp = idx >> 7, n = idx & 127;
            const float* s = W1e + (size_t)(2 * kp) * HID + ncol0 + n;
            bxv[t] = s[0]; byv[t] = s[HID];
        }
        for (int k0 = 0; k0 < HID; k0 += 16) {
            __syncthreads();
#pragma unroll
            for (int t = 0; t < 4; t++) {
                int idx = tid + t * 256, kp = idx >> 7, n = idx & 127;
                split_pair(bxv[t], byv[t], sm->Bhi[kp][n], sm->Blo[kp][n]);
            }
            __syncthreads();
            if (k0 + 16 < HID) {
#pragma unroll
                for (int t = 0; t < 4; t++) {
                    int idx = tid + t * 256, kp = idx >> 7, n = idx & 127;
                    const float* s = W1e + (size_t)(k0 + 16 + 2 * kp) * HID + ncol0 + n;
                    bxv[t] = s[0]; byv[t] = s[HID];
                }
            }
            const int kq = (k0 >> 1) + (lane & 3);
            const int kp = lane & 3;
            unsigned ah[2][4], al[2][4];
#pragma unroll
            for (int mt = 0; mt < 2; mt++) {
                int m = wm * 32 + mt * 16 + (lane >> 2);
                ah[mt][0] = sm->Ahi[m][kq];     ah[mt][1] = sm->Ahi[m + 8][kq];
                ah[mt][2] = sm->Ahi[m][kq + 4]; ah[mt][3] = sm->Ahi[m + 8][kq + 4];
                al[mt][0] = sm->Alo[m][kq];     al[mt][1] = sm->Alo[m + 8][kq];
                al[mt][2] = sm->Alo[m][kq + 4]; al[mt][3] = sm->Alo[m + 8][kq + 4];
            }
#pragma unroll
            for (int nt = 0; nt < 8; nt++) {
                int n = wn * 64 + nt * 8 + (lane >> 2);
                unsigned bh0 = sm->Bhi[kp][n], bh1 = sm->Bhi[kp + 4][n];
                unsigned bl0 = sm->Blo[kp][n], bl1 = sm->Blo[kp + 4][n];
#pragma unroll
                for (int mt = 0; mt < 2; mt++) {
                    mma16(acc[mt][nt], ah[mt], bh0, bh1);
                    mma16(acc[mt][nt], ah[mt], bl0, bl1);
                    mma16(acc[mt][nt], al[mt], bh0, bh1);
                }
            }
        }
        // epilogue B: D1 + energy partials
#pragma unroll
        for (int mt = 0; mt < 2; mt++) {
#pragma unroll
            for (int nt = 0; nt < 8; nt++) {
                float* cc = acc[mt][nt];
                int rloc = wm * 32 + mt * 16 + (lane >> 2);
                int gc = ncol0 + wn * 64 + nt * 8 + (lane & 3) * 2;
                float2 b = *(const float2*)&dp_b1[e * HID + gc];
                float2 w = *(const float2*)&dp_w2[e * HID + gc];
                float h0 = tanhf(cc[0] + b.x);
                float h1 = tanhf(cc[1] + b.y);
                float h2 = tanhf(cc[2] + b.x);
                float h3 = tanhf(cc[3] + b.y);
                size_t r0i = (size_t)(row0 + rloc) * HID + gc;
                size_t r1i = (size_t)(row0 + rloc + 8) * HID + gc;
                d_D1[r0i]     = w.x * (1.f - h0 * h0);
                d_D1[r0i + 1] = w.y * (1.f - h1 * h1);
                d_D1[r1i]     = w.x * (1.f - h2 * h2);
                d_D1[r1i + 1] = w.y * (1.f - h3 * h3);
                erow[mt][0] += h0 * w.x + h1 * w.y;
                erow[mt][1] += h2 * w.x + h3 * w.y;
            }
        }
    }
    // rowE reduction (one block owns each row -> plain store at the end)
#pragma unroll
    for (int mt = 0; mt < 2; mt++)
#pragma unroll
        for (int h = 0; h < 2; h++) {
            float v = erow[mt][h];
            v += __shfl_xor_sync(0xffffffffu, v, 1);
            v += __shfl_xor_sync(0xffffffffu, v, 2);
            if ((lane & 3) == 0)
                atomicAdd(&sm->srow[wm * 32 + mt * 16 + (lane >> 2) + h * 8], v);
        }
    __syncthreads();
    if (tid < 128) d_rowE[row0 + tid] = sm->srow[tid];
}

// ======================= fused BACKWARD (L2+L3) =============================
__global__ __launch_bounds__(256)
void k_bwd() {
    extern __shared__ char smraw[];
    SmemT* sm = reinterpret_cast<SmemT*>(smraw);

    const int row0 = blockIdx.x * 128;
    if (row0 >= d_off[NELEM]) return;
    int e = 0;
#pragma unroll
    for (int t = 0; t < NELEM - 1; t++)
        if (row0 >= d_off[t + 1]) e = t + 1;

    const int tid = threadIdx.x, lane = tid & 31, wid = tid >> 5;
    const int wm = wid & 3, wn = wid >> 2;

    if (tid < 128) sm->perm[tid] = d_perm[row0 + tid];
    __syncthreads();

    const int frow = tid >> 1, fhalf = tid & 1;
    const float* asrc = d_D1 + (size_t)(row0 + frow) * HID + fhalf * 8;
    const float* W1Te = d_W1T + (size_t)e * HID * HID;
    const float* W0Te = d_W0T + (size_t)e * HID * INDIM;

    // ---------------- phase A: D0 = (D1@W1T)*(1-H0^2) -> smem only ----------
    for (int nc2 = 0; nc2 < 2; nc2++) {
        const int ncol0 = nc2 * 128;
        float acc[2][8][4];
#pragma unroll
        for (int mt = 0; mt < 2; mt++)
#pragma unroll
            for (int nt = 0; nt < 8; nt++)
#pragma unroll
                for (int j = 0; j < 4; j++) acc[mt][nt][j] = 0.f;

        float4 avA[2];
        float bxv[4], byv[4];
        avA[0] = *(const float4*)(asrc);
        avA[1] = *(const float4*)(asrc + 4);
#pragma unroll
        for (int t = 0; t < 4; t++) {
            int idx = tid + t * 256, kp = idx >> 7, n = idx & 127;
            const float* s = W1Te + (size_t)(2 * kp) * HID + ncol0 + n;
            bxv[t] = s[0]; byv[t] = s[HID];
        }
        for (int k0 = 0; k0 < HID; k0 += 16) {
            __syncthreads();
            {
                const int kpb = fhalf * 4;
                split_pair(avA[0].x, avA[0].y, sm->Fhi[frow][kpb],     sm->Flo[frow][kpb]);
                split_pair(avA[0].z, avA[0].w, sm->Fhi[frow][kpb + 1], sm->Flo[frow][kpb + 1]);
                split_pair(avA[1].x, avA[1].y, sm->Fhi[frow][kpb + 2], sm->Flo[frow][kpb + 2]);
                split_pair(avA[1].z, avA[1].w, sm->Fhi[frow][kpb + 3], sm->Flo[frow][kpb + 3]);
            }
#pragma unroll
            for (int t = 0; t < 4; t++) {
                int idx = tid + t * 256, kp = idx >> 7, n = idx & 127;
                split_pair(bxv[t], byv[t], sm->Bhi[kp][n], sm->Blo[kp][n]);
            }
            __syncthreads();
            if (k0 + 16 < HID) {
                const float* s2 = asrc + k0 + 16;
                avA[0] = *(const float4*)(s2);
                avA[1] = *(const float4*)(s2 + 4);
#pragma unroll
                for (int t = 0; t < 4; t++) {
                    int idx = tid + t * 256, kp = idx >> 7, n = idx & 127;
                    const float* s = W1Te + (size_t)(k0 + 16 + 2 * kp) * HID + ncol0 + n;
                    bxv[t] = s[0]; byv[t] = s[HID];
                }
            }
            unsigned ah[2][4], al[2][4];
            const int kp = lane & 3;
#pragma unroll
            for (int mt = 0; mt < 2; mt++) {
                int m = wm * 32 + mt * 16 + (lane >> 2);
                ah[mt][0] = sm->Fhi[m][kp];     ah[mt][1] = sm->Fhi[m + 8][kp];
                ah[mt][2] = sm->Fhi[m][kp + 4]; ah[mt][3] = sm->Fhi[m + 8][kp + 4];
                al[mt][0] = sm->Flo[m][kp];     al[mt][1] = sm->Flo[m + 8][kp];
                al[mt][2] = sm->Flo[m][kp + 4]; al[mt][3] = sm->Flo[m + 8][kp + 4];
            }
#pragma unroll
            for (int nt = 0; nt < 8; nt++) {
                int n = wn * 64 + nt * 8 + (lane >> 2);
                unsigned bh0 = sm->Bhi[kp][n], bh1 = sm->Bhi[kp + 4][n];
                unsigned bl0 = sm->Blo[kp][n], bl1 = sm->Blo[kp + 4][n];
#pragma unroll
                for (int mt = 0; mt < 2; mt++) {
                    mma16(acc[mt][nt], ah[mt], bh0, bh1);
                    mma16(acc[mt][nt], ah[mt], bl0, bl1);
                    mma16(acc[mt][nt], al[mt], bh0, bh1);
                }
            }
        }
        // epilogue A: D0 -> persistent smem (never global)
#pragma unroll
        for (int mt = 0; mt < 2; mt++) {
#pragma unroll
            for (int nt = 0; nt < 8; nt++) {
                float* cc = acc[mt][nt];
                int rloc = wm * 32 + mt * 16 + (lane >> 2);
                int gc = ncol0 + wn * 64 + nt * 8 + (lane & 3) * 2;
                size_t r0i = (size_t)(row0 + rloc) * HID + gc;
                size_t r1i = (size_t)(row0 + rloc + 8) * HID + gc;
                float2 p = *(const float2*)&d_H0[r0i];
                float2 q = *(const float2*)&d_H0[r1i];
                float v0 = cc[0] * (1.f - p.x * p.x);
                float v1 = cc[1] * (1.f - p.y * p.y);
                float v2 = cc[2] * (1.f - q.x * q.x);
                float v3 = cc[3] * (1.f - q.y * q.y);
                int kq = gc >> 1;
                split_pair(v0, v1, sm->Ahi[rloc][kq],     sm->Alo[rloc][kq]);
                split_pair(v2, v3, sm->Ahi[rloc + 8][kq], sm->Alo[rloc + 8][kq]);
            }
        }
    }
    __syncthreads();   // D0 smem complete

    // ---------------- phase B: G = D0 @ W0T (ND=128), scatter ---------------
    {
        float acc[2][8][4];
#pragma unroll
        for (int mt = 0; mt < 2; mt++)
#pragma unroll
            for (int nt = 0; nt < 8; nt++)
#pragma unroll
                for (int j = 0; j < 4; j++) acc[mt][nt][j] = 0.f;

        float bxv[4], byv[4];
#pragma unroll
        for (int t = 0; t < 4; t++) {
            int idx = tid + t * 256, kp = idx >> 7, n = idx & 127;
            const float* s = W0Te + (size_t)(2 * kp) * INDIM + n;
            bxv[t] = s[0]; byv[t] = s[INDIM];
        }
        for (int k0 = 0; k0 < HID; k0 += 16) {
            __syncthreads();
#pragma unroll
            for (int t = 0; t < 4; t++) {
                int idx = tid + t * 256, kp = idx >> 7, n = idx & 127;
                split_pair(bxv[t], byv[t], sm->Bhi[kp][n], sm->Blo[kp][n]);
            }
            __syncthreads();
            if (k0 + 16 < HID) {
#pragma unroll
                for (int t = 0; t < 4; t++) {
                    int idx = tid + t * 256, kp = idx >> 7, n = idx & 127;
                    const float* s = W0Te + (size_t)(k0 + 16 + 2 * kp) * INDIM + n;
                    bxv[t] = s[0]; byv[t] = s[INDIM];
                }
            }
            const int kq = (k0 >> 1) + (lane & 3);
            const int kp = lane & 3;
            unsigned ah[2][4], al[2][4];
#pragma unroll
            for (int mt = 0; mt < 2; mt++) {
                int m = wm * 32 + mt * 16 + (lane >> 2);
                ah[mt][0] = sm->Ahi[m][kq];     ah[mt][1] = sm->Ahi[m + 8][kq];
                ah[mt][2] = sm->Ahi[m][kq + 4]; ah[mt][3] = sm->Ahi[m + 8][kq + 4];
                al[mt][0] = sm->Alo[m][kq];     al[mt][1] = sm->Alo[m + 8][kq];
                al[mt][2] = sm->Alo[m][kq + 4]; al[mt][3] = sm->Alo[m + 8][kq + 4];
            }
#pragma unroll
            for (int nt = 0; nt < 8; nt++) {
                int n = wn * 64 + nt * 8 + (lane >> 2);
                unsigned bh0 = sm->Bhi[kp][n], bh1 = sm->Bhi[kp + 4][n];
                unsigned bl0 = sm->Blo[kp][n], bl1 = sm->Blo[kp + 4][n];
#pragma unroll
                for (int mt = 0; mt < 2; mt++) {
                    mma16(acc[mt][nt], ah[mt], bh0, bh1);
                    mma16(acc[mt][nt], ah[mt], bl0, bl1);
                    mma16(acc[mt][nt], al[mt], bh0, bh1);
                }
            }
        }
        // epilogue: scatter G rows by perm
#pragma unroll
        for (int mt = 0; mt < 2; mt++) {
#pragma unroll
            for (int nt = 0; nt < 8; nt++) {
                float* cc = acc[mt][nt];
                int rloc = wm * 32 + mt * 16 + (lane >> 2);
                int c = wn * 64 + nt * 8 + (lane & 3) * 2;
                int a0 = sm->perm[rloc];
                int a1 = sm->perm[rloc + 8];
                if (a0 >= 0) {
                    d_G[(size_t)a0 * INDIM + c]     = cc[0];
                    d_G[(size_t)a0 * INDIM + c + 1] = cc[1];
                }
                if (a1 >= 0) {
                    d_G[(size_t)a1 * INDIM + c]     = cc[2];
                    d_G[(size_t)a1 * INDIM + c + 1] = cc[3];
                }
            }
        }
    }
}

// ---------------- energy segment sum ----------------
__global__ void k_energy(const float* __restrict__ b2, float* __restrict__ out) {
    int r = blockIdx.x * blockDim.x + threadIdx.x;
    if (r >= NPAD || r >= d_off[NELEM]) return;
    int atom = d_perm[r];
    if (atom < 0) return;
    int e = 0;
#pragma unroll
    for (int t = 0; t < NELEM - 1; t++)
        if (r >= d_off[t + 1]) e = t + 1;
    atomicAdd(&out[ld_idx(dp_img, atom, d_is64[0])], d_rowE[r] + b2[e]);
}

// ---------------- sparse transpose scatter ----------------
__global__ void k_sparse(float* __restrict__ out) {
    int i = blockIdx.x * blockDim.x + threadIdx.x;
    if (i < NNZV) {
        int is64 = d_is64[1];
        float g = d_G[ld_idx(dp_rows, i, is64)];
        atomicAdd(&out[NIMG + ld_idx(dp_cols, i, is64)], -dp_vals[i] * g);
    }
}

// ---------------- launch ----------------
extern "C" void kernel_launch(void* const* d_in, const int* in_sizes, int n_in,
                              void* d_out, int out_size) {
    int i_fp = 0, i_W0 = 6, i_W1 = 8, i_b2 = 11;
    int p50[2] = {1, 2};
    int p2M[3] = {3, 4, 5};
    int p1k[3] = {7, 9, 10};

    {
        int fp = -1, w0 = -1, w1 = -1, b2p = -1;
        int c50[2], n50 = 0, c2M[3], n2M = 0, c1k[3], n1k = 0;
        for (int i = 0; i < n_in; i++) {
            int s = in_sizes[i];
            if (s == 6400000) fp = i;
            else if (s == 131072) w0 = i;
            else if (s == 262144) w1 = i;
            else if (s == 4) b2p = i;
            else if (s == 50000 || s == 100000) { if (n50 < 2) c50[n50++] = i; }
            else if (s == 2000000 || s == 4000000) { if (n2M < 3) c2M[n2M++] = i; }
            else if (s == 1024) { if (n1k < 3) c1k[n1k++] = i; }
        }
        if (fp >= 0 && w0 >= 0 && w1 >= 0 && b2p >= 0 &&
            n50 == 2 && n2M == 3 && n1k == 3) {
            i_fp = fp; i_W0 = w0; i_W1 = w1; i_b2 = b2p;
            p50[0] = c50[0]; p50[1] = c50[1];
            p2M[0] = c2M[0]; p2M[1] = c2M[1]; p2M[2] = c2M[2];
            p1k[0] = c1k[0]; p1k[1] = c1k[1]; p1k[2] = c1k[2];
        }
    }

    const float* fp = (const float*)d_in[i_fp];
    const float* W0 = (const float*)d_in[i_W0];
    const float* W1 = (const float*)d_in[i_W1];
    const float* b2 = (const float*)d_in[i_b2];
    float* out = (float*)d_out;
    (void)out_size;

    static int attr_done = 0;
    if (!attr_done) {
        cudaFuncSetAttribute(k_fwd, cudaFuncAttributeMaxDynamicSharedMemorySize, SMT_BYTES);
        cudaFuncSetAttribute(k_bwd, cudaFuncAttributeMaxDynamicSharedMemorySize, SMT_BYTES);
        attr_done = 1;
    }

    k_detect<<<1, 256>>>((const int*)d_in[p50[0]], (const int*)d_in[p50[1]],
                         (const int*)d_in[p2M[0]], (const int*)d_in[p2M[1]],
                         (const int*)d_in[p2M[2]],
                         (const float*)d_in[p1k[0]], (const float*)d_in[p1k[1]],
                         (const float*)d_in[p1k[2]]);
    k_zero_init<<<(OUTSZ + 255) / 256, 256>>>(out);
    k_count<<<(NATOMS + 255) / 256, 256>>>();
    k_scatter<<<(NATOMS + 255) / 256, 256>>>();
    {
        int ntr = NELEM * HID * INDIM + NELEM * HID * HID;
        k_transpose<<<(ntr + 255) / 256, 256>>>(W0, W1);
    }

    k_fwd<<<NT128, 256, SMT_BYTES>>>(fp, W0, W1);    // H0 + H1/D1 + rowE
    k_energy<<<(NPAD + 255) / 256, 256>>>(b2, out);  // energy
    k_bwd<<<NT128, 256, SMT_BYTES>>>();              // D0 (smem-only) + G
    k_sparse<<<(NNZV + 255) / 256, 256>>>(out);      // forces
}

// round 15
// speedup vs baseline: 1.2274x; 1.2274x over previous
#include <cuda_runtime.h>
#include <cuda_bf16.h>
#include <cuda_fp16.h>
#include <cstdint>

#define NATOMS 50000
#define INDIM  128
#define HID    256
#define NELEM  4
#define NIMG   500
#define NNZV   2000000
#define NPAD   50560            // 395 * 128 >= NATOMS + 4*127
#define NT128  (NPAD / 128)     // 395
#define OUTSZ  (NIMG + 3 * NATOMS)

// ---------------- device scratch (referenced ONLY in device code) ----------
__device__ float d_H0[(size_t)NPAD * HID];
__device__ float d_H1[(size_t)NPAD * HID];   // D0 (L2 output, L3 input)
__device__ float d_D1[(size_t)NPAD * HID];
__device__ float d_G[(size_t)NATOMS * INDIM];
__device__ float d_rowE[NPAD];
__device__ float d_W0T[NELEM * HID * INDIM]; // [e][h][d]
__device__ float d_W1T[NELEM * HID * HID];   // [e][j][i]
__device__ int   d_perm[NPAD];
__device__ int   d_cnt[NELEM];
__device__ int   d_cur[NELEM];
__device__ int   d_off[NELEM + 1];
__device__ int   d_is64[2];

__device__ const int*   dp_an;
__device__ const int*   dp_img;
__device__ const int*   dp_rows;
__device__ const int*   dp_cols;
__device__ const float* dp_vals;
__device__ const float* dp_b0;
__device__ const float* dp_b1;
__device__ const float* dp_w2;

__device__ __forceinline__ int ld_idx(const int* __restrict__ p, int i, int is64) {
    return p[is64 ? (2 * i) : i];
}
__device__ __forceinline__ int emap(int z) {
    return z == 1 ? 0 : (z == 6 ? 1 : (z == 8 ? 2 : 3));
}
__device__ __forceinline__ bool in_elem_set(int v) {
    return v == 1 || v == 6 || v == 8 || v == 29;
}
__device__ __forceinline__ unsigned bpack(float x, float y) {
    __nv_bfloat162 t = __floats2bfloat162_rn(x, y);
    return *reinterpret_cast<unsigned*>(&t);
}
__device__ __forceinline__ unsigned hpack(float x, float y) {
    __half2 t = __floats2half2_rn(x, y);
    return *reinterpret_cast<unsigned*>(&t);
}
__device__ __forceinline__ void split_pair(float x, float y,
                                           unsigned& hi, unsigned& lo) {
    float hx = __bfloat162float(__float2bfloat16(x));
    float hy = __bfloat162float(__float2bfloat16(y));
    hi = bpack(hx, hy);
    lo = bpack(x - hx, y - hy);
}
// bf16 mma (3-pass forward path)
__device__ __forceinline__ void mma16(float* c, const unsigned* a,
                                      unsigned b0, unsigned b1) {
    asm volatile(
        "mma.sync.aligned.m16n8k16.row.col.f32.bf16.bf16.f32 "
        "{%0,%1,%2,%3}, {%4,%5,%6,%7}, {%8,%9}, {%0,%1,%2,%3};"
        : "+f"(c[0]), "+f"(c[1]), "+f"(c[2]), "+f"(c[3])
        : "r"(a[0]), "r"(a[1]), "r"(a[2]), "r"(a[3]), "r"(b0), "r"(b1));
}
// fp16 mma (1-pass backward path, 11 mantissa bits)
__device__ __forceinline__ void mma16h(float* c, const unsigned* a,
                                       unsigned b0, unsigned b1) {
    asm volatile(
        "mma.sync.aligned.m16n8k16.row.col.f32.f16.f16.f32 "
        "{%0,%1,%2,%3}, {%4,%5,%6,%7}, {%8,%9}, {%0,%1,%2,%3};"
        : "+f"(c[0]), "+f"(c[1]), "+f"(c[2]), "+f"(c[3])
        : "r"(a[0]), "r"(a[1]), "r"(a[2]), "r"(a[3]), "r"(b0), "r"(b1));
}

// ---------------- input identification (+ counter reset) ----------------
__global__ void k_detect(const int* pa, const int* pb,
                         const int* q0, const int* q1, const int* q2,
                         const float* r0, const float* r1, const float* r2) {
    __shared__ int s_anfail[2];
    __shared__ int s_isf[3];
    __shared__ int s_qmax[3];
    __shared__ int s_bmax[3];
    int tid = threadIdx.x;
    if (tid < 2) s_anfail[tid] = 0;
    if (tid < 3) { s_isf[tid] = 0; s_qmax[tid] = 0; s_bmax[tid] = 0; }
    if (tid < NELEM) { d_cnt[tid] = 0; d_cur[tid] = 0; }
    __syncthreads();

    const int* pp[2] = {pa, pb};
    const int* qq[3] = {q0, q1, q2};
    const float* rr[3] = {r0, r1, r2};

    if (tid < 32) {
        int c = tid >> 4;
        int i = tid & 15;
        if (!in_elem_set(pp[c][2 * i])) atomicExch(&s_anfail[c], 1);
    }
    for (int j = 0; j < 3; j++) {
        const int* q = qq[j];
        for (int i = tid; i < 1024; i += blockDim.x) {
            int w = q[i];
            if (w < 0 || w > 0x30000000) atomicExch(&s_isf[j], 1);
            atomicMax(&s_qmax[j], w);
        }
    }
    for (int j = 0; j < 3; j++) {
        const float* r = rr[j];
        for (int i = tid; i < 1024; i += blockDim.x) {
            float v = fabsf(r[i]);
            atomicMax(&s_bmax[j], __float_as_int(v));
        }
    }
    __syncthreads();

    if (tid == 0) {
        int asel = s_anfail[0] ? (s_anfail[1] ? 0 : 1) : 0;
        dp_an  = pp[asel];
        dp_img = pp[1 - asel];
        d_is64[0] = (pp[asel][1] == 0 && pp[asel][3] == 0 && pp[asel][5] == 0) ? 1 : 0;

        int vsel = 2;
        if (s_isf[0]) vsel = 0; else if (s_isf[1]) vsel = 1; else if (s_isf[2]) vsel = 2;
        int o1 = (vsel == 0) ? 1 : 0;
        int o2 = (vsel == 2) ? 1 : 2;
        int rsel = (s_qmax[o1] >= s_qmax[o2]) ? o1 : o2;
        int csel = o1 + o2 - rsel;
        dp_vals = (const float*)qq[vsel];
        dp_rows = qq[rsel];
        dp_cols = qq[csel];
        const int* rw = qq[rsel];
        d_is64[1] = (rw[1] == 0 && rw[3] == 0 && rw[5] == 0 && rw[7] == 0 &&
                     rw[9] == 0 && rw[11] == 0) ? 1 : 0;

        int b0s;
        if (s_bmax[0] >= s_bmax[1] && s_bmax[0] >= s_bmax[2]) b0s = 0;
        else if (s_bmax[1] >= s_bmax[2]) b0s = 1;
        else b0s = 2;
        int b1s = (b0s + 1) % 3;
        int w2s = (b0s + 2) % 3;
        dp_b0 = rr[b0s]; dp_b1 = rr[b1s]; dp_w2 = rr[w2s];
    }
}

// ---------------- prep: zero out/perm/rowE + element count -----------------
__global__ void k_prep(float* out) {
    __shared__ int sc[NELEM];
    int tid = threadIdx.x;
    if (tid < NELEM) sc[tid] = 0;
    __syncthreads();
    int i = blockIdx.x * blockDim.x + tid;
    if (i < OUTSZ) out[i] = 0.f;
    if (i < NPAD) { d_perm[i] = -1; d_rowE[i] = 0.f; }
    if (i < NATOMS) atomicAdd(&sc[emap(ld_idx(dp_an, i, d_is64[0]))], 1);
    __syncthreads();
    if (tid < NELEM && sc[tid] > 0) atomicAdd(&d_cnt[tid], sc[tid]);
}

// scatter with per-block locally recomputed offsets
__global__ void k_scatter() {
    __shared__ int lc[NELEM], base[NELEM], loff[NELEM];
    int tid = threadIdx.x;
    if (tid < NELEM) lc[tid] = 0;
    __syncthreads();
    if (tid == 0) {
        int o = 0;
        for (int e2 = 0; e2 < NELEM; e2++) {
            loff[e2] = o;
            o += ((d_cnt[e2] + 127) / 128) * 128;
        }
        if (blockIdx.x == 0) {
            for (int e2 = 0; e2 < NELEM; e2++) d_off[e2] = loff[e2];
            d_off[NELEM] = o;
        }
    }
    __syncthreads();
    int i = blockIdx.x * blockDim.x + tid;
    int e = -1, rank = 0;
    if (i < NATOMS) {
        e = emap(ld_idx(dp_an, i, d_is64[0]));
        rank = atomicAdd(&lc[e], 1);
    }
    __syncthreads();
    if (tid < NELEM && lc[tid] > 0) base[tid] = atomicAdd(&d_cur[tid], lc[tid]);
    __syncthreads();
    if (i < NATOMS) d_perm[loff[e] + base[e] + rank] = i;
}

__global__ void k_transpose(const float* __restrict__ W0,
                            const float* __restrict__ W1) {
    const int n0 = NELEM * HID * INDIM;
    const int n1 = NELEM * HID * HID;
    int i = blockIdx.x * blockDim.x + threadIdx.x;
    if (i < n0) {
        int d = i % INDIM;
        int t = i / INDIM;
        int h = t % HID;
        int e = t / HID;
        d_W0T[i] = W0[((size_t)e * INDIM + d) * HID + h];
    } else if (i < n0 + n1) {
        int k = i - n0;
        int i2 = k % HID;
        int t = k / HID;
        int j = t % HID;
        int e = t / HID;
        d_W1T[k] = W1[((size_t)e * HID + i2) * HID + j];
    }
}

// ---------------- tensor-core GEMM, register-prefetch pipelined -------------
// PASSES=3: bf16 hi/lo split, 3-pass compensated (~fp32) — forward/energy.
// PASSES=1: plain fp16 (11 mantissa bits) — backward/forces only.
// L=0: H0 = tanh(FP[perm] @ W0 + b0)       KD=128 ND=256  P=3
// L=1: D1 = w2*(1-h1^2) + rowE             KD=256 ND=256  P=3
// L=2: D0 = (D1 @ W1T) * (1 - H0^2)        KD=256 ND=256  P=1
// L=3: G[perm] = D0 @ W0T (scatter)        KD=256 ND=128  P=1
#define SAN 20
#define SBN 136

template <int L, int PASSES>
__global__ __launch_bounds__(256)
void k_gemm_tc(const float* __restrict__ Aarg, const float* __restrict__ Warg) {
    constexpr int KD = (L == 0) ? INDIM : HID;
    constexpr int ND = (L == 3) ? INDIM : HID;

    const int row0 = blockIdx.x * 128;
    if (row0 >= d_off[NELEM]) return;
    int e = 0;
#pragma unroll
    for (int t = 0; t < NELEM - 1; t++)
        if (row0 >= d_off[t + 1]) e = t + 1;
    const int ncol0 = blockIdx.y * 128;

    __shared__ unsigned As_hi[128][SAN];
    __shared__ unsigned As_lo[PASSES == 3 ? 128 : 8][SAN];
    __shared__ unsigned Bs_hi[8][SBN];
    __shared__ unsigned Bs_lo[PASSES == 3 ? 8 : 1][SBN];
    __shared__ int sPerm[128];
    __shared__ float s_row[128];

    const int tid  = threadIdx.x;
    const int lane = tid & 31;
    const int wid  = tid >> 5;
    const int wm   = wid & 3;
    const int wn   = wid >> 2;

    if (tid < 128) {
        sPerm[tid] = d_perm[row0 + tid];
        if (L == 1) s_row[tid] = 0.f;
    }
    __syncthreads();

    const float* A = (L == 0) ? Aarg
                   : (L == 1) ? (const float*)d_H0
                   : (L == 2) ? (const float*)d_D1
                              : (const float*)d_H1;
    const float* Wb = (L <= 1) ? (Warg + (size_t)e * KD * ND)
                    : (L == 2) ? (d_W1T + (size_t)e * HID * HID)
                               : (d_W0T + (size_t)e * HID * INDIM);

    float acc[2][8][4];
#pragma unroll
    for (int mt = 0; mt < 2; mt++)
#pragma unroll
        for (int nt = 0; nt < 8; nt++)
#pragma unroll
            for (int j = 0; j < 4; j++) acc[mt][nt][j] = 0.f;

    const int arow  = tid >> 1;
    const int ahalf = tid & 1;

    float4 avA[2];
    float bxv[4], byv[4];
    bool avalid = true;

    // ---- preload chunk 0 ----
    {
        if (L == 0) {
            int g = sPerm[arow];
            avalid = (g >= 0);
            const float* src = A + (size_t)(avalid ? g : 0) * KD + ahalf * 8;
            avA[0] = avalid ? *(const float4*)(src)     : make_float4(0,0,0,0);
            avA[1] = avalid ? *(const float4*)(src + 4) : make_float4(0,0,0,0);
        } else {
            const float* src = A + (size_t)(row0 + arow) * KD + ahalf * 8;
            avA[0] = *(const float4*)(src);
            avA[1] = *(const float4*)(src + 4);
        }
#pragma unroll
        for (int t = 0; t < 4; t++) {
            int idx = tid + t * 256;
            int kp = idx >> 7;
            int n  = idx & 127;
            const float* s = Wb + (size_t)(2 * kp) * ND + ncol0 + n;
            bxv[t] = s[0];
            byv[t] = s[ND];
        }
    }

    for (int k0 = 0; k0 < KD; k0 += 16) {
        __syncthreads();
        // ---- store current chunk ----
#pragma unroll
        for (int j2 = 0; j2 < 2; j2++) {
            int kp = ahalf * 4 + j2 * 2;
            float4 v = avA[j2];
            if (PASSES == 3) {
                split_pair(v.x, v.y, As_hi[arow][kp],     As_lo[arow][kp]);
                split_pair(v.z, v.w, As_hi[arow][kp + 1], As_lo[arow][kp + 1]);
            } else {
                As_hi[arow][kp]     = hpack(v.x, v.y);
                As_hi[arow][kp + 1] = hpack(v.z, v.w);
            }
        }
#pragma unroll
        for (int t = 0; t < 4; t++) {
            int idx = tid + t * 256;
            int kp = idx >> 7;
            int n  = idx & 127;
            if (PASSES == 3) {
                split_pair(bxv[t], byv[t], Bs_hi[kp][n], Bs_lo[kp][n]);
            } else {
                Bs_hi[kp][n] = hpack(bxv[t], byv[t]);
            }
        }
        __syncthreads();

        // ---- preload next chunk while mma runs ----
        if (k0 + 16 < KD) {
            int kn = k0 + 16;
            if (L == 0) {
                const float* src = A + (size_t)(avalid ? sPerm[arow] : 0) * KD
                                   + kn + ahalf * 8;
                avA[0] = avalid ? *(const float4*)(src)     : make_float4(0,0,0,0);
                avA[1] = avalid ? *(const float4*)(src + 4) : make_float4(0,0,0,0);
            } else {
                const float* src = A + (size_t)(row0 + arow) * KD + kn + ahalf * 8;
                avA[0] = *(const float4*)(src);
                avA[1] = *(const float4*)(src + 4);
            }
#pragma unroll
            for (int t = 0; t < 4; t++) {
                int idx = tid + t * 256;
                int kp = idx >> 7;
                int n  = idx & 127;
                const float* s = Wb + (size_t)(kn + 2 * kp) * ND + ncol0 + n;
                bxv[t] = s[0];
                byv[t] = s[ND];
            }
        }

        // ---- fragments + mma ----
        unsigned ah[2][4], al[2][4];
        const int kp = lane & 3;
#pragma unroll
        for (int mt = 0; mt < 2; mt++) {
            int m = wm * 32 + mt * 16 + (lane >> 2);
            ah[mt][0] = As_hi[m][kp];
            ah[mt][1] = As_hi[m + 8][kp];
            ah[mt][2] = As_hi[m][kp + 4];
            ah[mt][3] = As_hi[m + 8][kp + 4];
            if (PASSES == 3) {
                al[mt][0] = As_lo[m][kp];
                al[mt][1] = As_lo[m + 8][kp];
                al[mt][2] = As_lo[m][kp + 4];
                al[mt][3] = As_lo[m + 8][kp + 4];
            }
        }
#pragma unroll
        for (int nt = 0; nt < 8; nt++) {
            int n = wn * 64 + nt * 8 + (lane >> 2);
            unsigned bh0 = Bs_hi[kp][n];
            unsigned bh1 = Bs_hi[kp + 4][n];
            if (PASSES == 3) {
                unsigned bl0 = Bs_lo[kp][n];
                unsigned bl1 = Bs_lo[kp + 4][n];
#pragma unroll
                for (int mt = 0; mt < 2; mt++) {
                    mma16(acc[mt][nt], ah[mt], bh0, bh1);
                    mma16(acc[mt][nt], ah[mt], bl0, bl1);
                    mma16(acc[mt][nt], al[mt], bh0, bh1);
                }
            } else {
#pragma unroll
                for (int mt = 0; mt < 2; mt++)
                    mma16h(acc[mt][nt], ah[mt], bh0, bh1);
            }
        }
    }

    // ---- epilogue ----
    float erow[2][2];
    if (L == 1) {
        erow[0][0] = erow[0][1] = erow[1][0] = erow[1][1] = 0.f;
    }
#pragma unroll
    for (int mt = 0; mt < 2; mt++) {
#pragma unroll
        for (int nt = 0; nt < 8; nt++) {
            float* cc = acc[mt][nt];
            int rloc = wm * 32 + mt * 16 + (lane >> 2);
            int c = ncol0 + wn * 64 + nt * 8 + (lane & 3) * 2;
            if (L == 0) {
                float2 b = *(const float2*)&dp_b0[e * ND + c];
                size_t r0i = (size_t)(row0 + rloc) * ND + c;
                size_t r1i = (size_t)(row0 + rloc + 8) * ND + c;
                d_H0[r0i]     = tanhf(cc[0] + b.x);
                d_H0[r0i + 1] = tanhf(cc[1] + b.y);
                d_H0[r1i]     = tanhf(cc[2] + b.x);
                d_H0[r1i + 1] = tanhf(cc[3] + b.y);
            } else if (L == 1) {
                float2 b = *(const float2*)&dp_b1[e * ND + c];
                float2 w = *(const float2*)&dp_w2[e * ND + c];
                size_t r0i = (size_t)(row0 + rloc) * ND + c;
                size_t r1i = (size_t)(row0 + rloc + 8) * ND + c;
                float h0 = tanhf(cc[0] + b.x);
                float h1 = tanhf(cc[1] + b.y);
                float h2 = tanhf(cc[2] + b.x);
                float h3 = tanhf(cc[3] + b.y);
                d_D1[r0i]     = w.x * (1.f - h0 * h0);
                d_D1[r0i + 1] = w.y * (1.f - h1 * h1);
                d_D1[r1i]     = w.x * (1.f - h2 * h2);
                d_D1[r1i + 1] = w.y * (1.f - h3 * h3);
                erow[mt][0] += h0 * w.x + h1 * w.y;
                erow[mt][1] += h2 * w.x + h3 * w.y;
            } else if (L == 2) {
                size_t r0i = (size_t)(row0 + rloc) * ND + c;
                size_t r1i = (size_t)(row0 + rloc + 8) * ND + c;
                float2 h0 = *(const float2*)&d_H0[r0i];
                float2 h1 = *(const float2*)&d_H0[r1i];
                d_H1[r0i]     = cc[0] * (1.f - h0.x * h0.x);
                d_H1[r0i + 1] = cc[1] * (1.f - h0.y * h0.y);
                d_H1[r1i]     = cc[2] * (1.f - h1.x * h1.x);
                d_H1[r1i + 1] = cc[3] * (1.f - h1.y * h1.y);
            } else {
                int a0 = sPerm[rloc];
                int a1 = sPerm[rloc + 8];
                if (a0 >= 0) {
                    d_G[(size_t)a0 * ND + c]     = cc[0];
                    d_G[(size_t)a0 * ND + c + 1] = cc[1];
                }
                if (a1 >= 0) {
                    d_G[(size_t)a1 * ND + c]     = cc[2];
                    d_G[(size_t)a1 * ND + c + 1] = cc[3];
                }
            }
        }
    }

    if (L == 1) {
#pragma unroll
        for (int mt = 0; mt < 2; mt++)
#pragma unroll
            for (int h = 0; h < 2; h++) {
                float v = erow[mt][h];
                v += __shfl_xor_sync(0xffffffffu, v, 1);
                v += __shfl_xor_sync(0xffffffffu, v, 2);
                if ((lane & 3) == 0) {
                    int rloc = wm * 32 + mt * 16 + (lane >> 2) + h * 8;
                    atomicAdd(&s_row[rloc], v);
                }
            }
        __syncthreads();
        if (tid < 128) atomicAdd(&d_rowE[row0 + tid], s_row[tid]);
    }
}

// ---------------- energy segment sum ----------------
__global__ void k_energy(const float* __restrict__ b2, float* __restrict__ out) {
    int r = blockIdx.x * blockDim.x + threadIdx.x;
    if (r >= NPAD || r >= d_off[NELEM]) return;
    int atom = d_perm[r];
    if (atom < 0) return;
    int e = 0;
#pragma unroll
    for (int t = 0; t < NELEM - 1; t++)
        if (r >= d_off[t + 1]) e = t + 1;
    atomicAdd(&out[ld_idx(dp_img, atom, d_is64[0])], d_rowE[r] + b2[e]);
}

// ---------------- sparse transpose scatter (2 nnz per thread) --------------
__global__ void k_sparse(float* __restrict__ out) {
    int i0 = (blockIdx.x * blockDim.x + threadIdx.x) * 2;
    const int is64 = d_is64[1];
    const int* rows = dp_rows;
    const int* cols = dp_cols;
    const float* vals = dp_vals;
#pragma unroll
    for (int j = 0; j < 2; j++) {
        int i = i0 + j;
        if (i < NNZV) {
            float g = d_G[ld_idx(rows, i, is64)];
            atomicAdd(&out[NIMG + ld_idx(cols, i, is64)], -vals[i] * g);
        }
    }
}

// ---------------- launch ----------------
extern "C" void kernel_launch(void* const* d_in, const int* in_sizes, int n_in,
                              void* d_out, int out_size) {
    int i_fp = 0, i_W0 = 6, i_W1 = 8, i_b2 = 11;
    int p50[2] = {1, 2};
    int p2M[3] = {3, 4, 5};
    int p1k[3] = {7, 9, 10};

    {
        int fp = -1, w0 = -1, w1 = -1, b2p = -1;
        int c50[2], n50 = 0, c2M[3], n2M = 0, c1k[3], n1k = 0;
        for (int i = 0; i < n_in; i++) {
            int s = in_sizes[i];
            if (s == 6400000) fp = i;
            else if (s == 131072) w0 = i;
            else if (s == 262144) w1 = i;
            else if (s == 4) b2p = i;
            else if (s == 50000 || s == 100000) { if (n50 < 2) c50[n50++] = i; }
            else if (s == 2000000 || s == 4000000) { if (n2M < 3) c2M[n2M++] = i; }
            else if (s == 1024) { if (n1k < 3) c1k[n1k++] = i; }
        }
        if (fp >= 0 && w0 >= 0 && w1 >= 0 && b2p >= 0 &&
            n50 == 2 && n2M == 3 && n1k == 3) {
            i_fp = fp; i_W0 = w0; i_W1 = w1; i_b2 = b2p;
            p50[0] = c50[0]; p50[1] = c50[1];
            p2M[0] = c2M[0]; p2M[1] = c2M[1]; p2M[2] = c2M[2];
            p1k[0] = c1k[0]; p1k[1] = c1k[1]; p1k[2] = c1k[2];
        }
    }

    const float* fp = (const float*)d_in[i_fp];
    const float* W0 = (const float*)d_in[i_W0];
    const float* W1 = (const float*)d_in[i_W1];
    const float* b2 = (const float*)d_in[i_b2];
    float* out = (float*)d_out;
    (void)out_size;

    k_detect<<<1, 256>>>((const int*)d_in[p50[0]], (const int*)d_in[p50[1]],
                         (const int*)d_in[p2M[0]], (const int*)d_in[p2M[1]],
                         (const int*)d_in[p2M[2]],
                         (const float*)d_in[p1k[0]], (const float*)d_in[p1k[1]],
                         (const float*)d_in[p1k[2]]);
    k_prep<<<(OUTSZ + 255) / 256, 256>>>(out);
    k_scatter<<<(NATOMS + 255) / 256, 256>>>();
    {
        int ntr = NELEM * HID * INDIM + NELEM * HID * HID;
        k_transpose<<<(ntr + 255) / 256, 256>>>(W0, W1);
    }

    dim3 gfull(NT128, 2);   // ND=256
    dim3 ghalf(NT128, 1);   // ND=128

    k_gemm_tc<0, 3><<<gfull, 256>>>(fp, W0);           // H0 (bf16 3-pass)
    k_gemm_tc<1, 3><<<gfull, 256>>>(nullptr, W1);      // D1 + rowE (bf16 3-pass)
    k_energy<<<(NPAD + 255) / 256, 256>>>(b2, out);    // energy
    k_gemm_tc<2, 1><<<gfull, 256>>>(nullptr, nullptr); // D0 (fp16 1-pass)
    k_gemm_tc<3, 1><<<ghalf, 256>>>(nullptr, nullptr); // G scatter (fp16 1-pass)
    k_sparse<<<(NNZV / 2 + 255) / 256, 256>>>(out);    // forces
}

// round 16
// speedup vs baseline: 1.4650x; 1.1936x over previous
#include <cuda_runtime.h>
#include <cuda_fp16.h>
#include <cstdint>

#define NATOMS 50000
#define INDIM  128
#define HID    256
#define NELEM  4
#define NIMG   500
#define NNZV   2000000
#define NPAD   50560            // 395 * 128 >= NATOMS + 4*127
#define NT128  (NPAD / 128)     // 395
#define OUTSZ  (NIMG + 3 * NATOMS)

// ---------------- device scratch (referenced ONLY in device code) ----------
__device__ float    d_H0[(size_t)NPAD * HID];
__device__ unsigned d_D1h[(size_t)NPAD * HID / 2];  // D1 as half2 (k-pairs)
__device__ unsigned d_H1h[(size_t)NPAD * HID / 2];  // D0 as half2
__device__ float    d_G[(size_t)NATOMS * INDIM];
__device__ float    d_W0T[NELEM * HID * INDIM];     // [e][h][d]
__device__ float    d_W1T[NELEM * HID * HID];       // [e][j][i]
__device__ int      d_perm[NPAD];
__device__ int      d_cnt[NELEM];
__device__ int      d_cur[NELEM];
__device__ int      d_off[NELEM + 1];
__device__ int      d_is64[2];

__device__ const int*   dp_an;
__device__ const int*   dp_img;
__device__ const int*   dp_rows;
__device__ const int*   dp_cols;
__device__ const float* dp_vals;
__device__ const float* dp_b0;
__device__ const float* dp_b1;
__device__ const float* dp_w2;

__device__ __forceinline__ int ld_idx(const int* __restrict__ p, int i, int is64) {
    return p[is64 ? (2 * i) : i];
}
__device__ __forceinline__ int emap(int z) {
    return z == 1 ? 0 : (z == 6 ? 1 : (z == 8 ? 2 : 3));
}
__device__ __forceinline__ bool in_elem_set(int v) {
    return v == 1 || v == 6 || v == 8 || v == 29;
}
__device__ __forceinline__ unsigned hpack(float x, float y) {
    __half2 t = __floats2half2_rn(x, y);
    return *reinterpret_cast<unsigned*>(&t);
}
// fp16 hi/lo split of a float pair (hi = fp16(x), lo = fp16(x - hi))
__device__ __forceinline__ void hsplit_pair(float x, float y,
                                            unsigned& hi, unsigned& lo) {
    float hx = __half2float(__float2half_rn(x));
    float hy = __half2float(__float2half_rn(y));
    hi = hpack(hx, hy);
    lo = hpack(x - hx, y - hy);
}
__device__ __forceinline__ void mma16h(float* c, const unsigned* a,
                                       unsigned b0, unsigned b1) {
    asm volatile(
        "mma.sync.aligned.m16n8k16.row.col.f32.f16.f16.f32 "
        "{%0,%1,%2,%3}, {%4,%5,%6,%7}, {%8,%9}, {%0,%1,%2,%3};"
        : "+f"(c[0]), "+f"(c[1]), "+f"(c[2]), "+f"(c[3])
        : "r"(a[0]), "r"(a[1]), "r"(a[2]), "r"(a[3]), "r"(b0), "r"(b1));
}

// ---------------- input identification (+ counter reset) ----------------
__global__ void k_detect(const int* pa, const int* pb,
                         const int* q0, const int* q1, const int* q2,
                         const float* r0, const float* r1, const float* r2) {
    __shared__ int s_anfail[2];
    __shared__ int s_isf[3];
    __shared__ int s_qmax[3];
    __shared__ int s_bmax[3];
    int tid = threadIdx.x;
    if (tid < 2) s_anfail[tid] = 0;
    if (tid < 3) { s_isf[tid] = 0; s_qmax[tid] = 0; s_bmax[tid] = 0; }
    if (tid < NELEM) { d_cnt[tid] = 0; d_cur[tid] = 0; }
    __syncthreads();

    const int* pp[2] = {pa, pb};
    const int* qq[3] = {q0, q1, q2};
    const float* rr[3] = {r0, r1, r2};

    if (tid < 32) {
        int c = tid >> 4;
        int i = tid & 15;
        if (!in_elem_set(pp[c][2 * i])) atomicExch(&s_anfail[c], 1);
    }
    for (int j = 0; j < 3; j++) {
        const int* q = qq[j];
        for (int i = tid; i < 1024; i += blockDim.x) {
            int w = q[i];
            if (w < 0 || w > 0x30000000) atomicExch(&s_isf[j], 1);
            atomicMax(&s_qmax[j], w);
        }
    }
    for (int j = 0; j < 3; j++) {
        const float* r = rr[j];
        for (int i = tid; i < 1024; i += blockDim.x) {
            float v = fabsf(r[i]);
            atomicMax(&s_bmax[j], __float_as_int(v));
        }
    }
    __syncthreads();

    if (tid == 0) {
        int asel = s_anfail[0] ? (s_anfail[1] ? 0 : 1) : 0;
        dp_an  = pp[asel];
        dp_img = pp[1 - asel];
        d_is64[0] = (pp[asel][1] == 0 && pp[asel][3] == 0 && pp[asel][5] == 0) ? 1 : 0;

        int vsel = 2;
        if (s_isf[0]) vsel = 0; else if (s_isf[1]) vsel = 1; else if (s_isf[2]) vsel = 2;
        int o1 = (vsel == 0) ? 1 : 0;
        int o2 = (vsel == 2) ? 1 : 2;
        int rsel = (s_qmax[o1] >= s_qmax[o2]) ? o1 : o2;
        int csel = o1 + o2 - rsel;
        dp_vals = (const float*)qq[vsel];
        dp_rows = qq[rsel];
        dp_cols = qq[csel];
        const int* rw = qq[rsel];
        d_is64[1] = (rw[1] == 0 && rw[3] == 0 && rw[5] == 0 && rw[7] == 0 &&
                     rw[9] == 0 && rw[11] == 0) ? 1 : 0;

        int b0s;
        if (s_bmax[0] >= s_bmax[1] && s_bmax[0] >= s_bmax[2]) b0s = 0;
        else if (s_bmax[1] >= s_bmax[2]) b0s = 1;
        else b0s = 2;
        int b1s = (b0s + 1) % 3;
        int w2s = (b0s + 2) % 3;
        dp_b0 = rr[b0s]; dp_b1 = rr[b1s]; dp_w2 = rr[w2s];
    }
}

// ---------------- prep: zero out/perm + element count ----------------------
__global__ void k_prep(float* out) {
    __shared__ int sc[NELEM];
    int tid = threadIdx.x;
    if (tid < NELEM) sc[tid] = 0;
    __syncthreads();
    int i = blockIdx.x * blockDim.x + tid;
    if (i < OUTSZ) out[i] = 0.f;
    if (i < NPAD) d_perm[i] = -1;
    if (i < NATOMS) atomicAdd(&sc[emap(ld_idx(dp_an, i, d_is64[0]))], 1);
    __syncthreads();
    if (tid < NELEM && sc[tid] > 0) atomicAdd(&d_cnt[tid], sc[tid]);
}

__global__ void k_scatter() {
    __shared__ int lc[NELEM], base[NELEM], loff[NELEM];
    int tid = threadIdx.x;
    if (tid < NELEM) lc[tid] = 0;
    __syncthreads();
    if (tid == 0) {
        int o = 0;
        for (int e2 = 0; e2 < NELEM; e2++) {
            loff[e2] = o;
            o += ((d_cnt[e2] + 127) / 128) * 128;
        }
        if (blockIdx.x == 0) {
            for (int e2 = 0; e2 < NELEM; e2++) d_off[e2] = loff[e2];
            d_off[NELEM] = o;
        }
    }
    __syncthreads();
    int i = blockIdx.x * blockDim.x + tid;
    int e = -1, rank = 0;
    if (i < NATOMS) {
        e = emap(ld_idx(dp_an, i, d_is64[0]));
        rank = atomicAdd(&lc[e], 1);
    }
    __syncthreads();
    if (tid < NELEM && lc[tid] > 0) base[tid] = atomicAdd(&d_cur[tid], lc[tid]);
    __syncthreads();
    if (i < NATOMS) d_perm[loff[e] + base[e] + rank] = i;
}

__global__ void k_transpose(const float* __restrict__ W0,
                            const float* __restrict__ W1) {
    const int n0 = NELEM * HID * INDIM;
    const int n1 = NELEM * HID * HID;
    int i = blockIdx.x * blockDim.x + threadIdx.x;
    if (i < n0) {
        int d = i % INDIM;
        int t = i / INDIM;
        int h = t % HID;
        int e = t / HID;
        d_W0T[i] = W0[((size_t)e * INDIM + d) * HID + h];
    } else if (i < n0 + n1) {
        int k = i - n0;
        int i2 = k % HID;
        int t = k / HID;
        int j = t % HID;
        int e = t / HID;
        d_W1T[k] = W1[((size_t)e * HID + i2) * HID + j];
    }
}

// ---------------- fp16 tensor-core GEMM, register-prefetch pipelined --------
// PASSES=2: A split fp16 hi/lo (2-pass), B 1-pass fp16  — forward.
// PASSES=1: plain fp16 (A already half2 in memory)       — backward.
// L=0: H0 = tanh(FP[perm] @ W0 + b0)                 KD=128 ND=256  P=2
// L=1: D1h = w2*(1-h1^2); energy atomics (fused)     KD=256 ND=256  P=2
// L=2: D0h = (D1h @ W1T) * (1 - H0^2)                KD=256 ND=256  P=1
// L=3: G[perm] = D0h @ W0T (scatter)                 KD=256 ND=128  P=1
#define SAN 20
#define SBN 136

template <int L, int PASSES>
__global__ __launch_bounds__(256)
void k_gemm_tc(const float* __restrict__ Aarg, const float* __restrict__ Warg,
               float* __restrict__ Carg) {
    constexpr int KD = (L == 0) ? INDIM : HID;
    constexpr int ND = (L == 3) ? INDIM : HID;
    constexpr bool AHALF = (L >= 2);

    const int row0 = blockIdx.x * 128;
    if (row0 >= d_off[NELEM]) return;
    int e = 0;
#pragma unroll
    for (int t = 0; t < NELEM - 1; t++)
        if (row0 >= d_off[t + 1]) e = t + 1;
    const int ncol0 = blockIdx.y * 128;

    __shared__ unsigned As_hi[128][SAN];
    __shared__ unsigned As_lo[PASSES == 2 ? 128 : 8][SAN];
    __shared__ unsigned Bs_hi[8][SBN];
    __shared__ int sPerm[128];
    __shared__ float s_row[128];

    const int tid  = threadIdx.x;
    const int lane = tid & 31;
    const int wid  = tid >> 5;
    const int wm   = wid & 3;
    const int wn   = wid >> 2;

    if (tid < 128) {
        sPerm[tid] = d_perm[row0 + tid];
        if (L == 1) s_row[tid] = 0.f;
    }
    __syncthreads();

    const float* A = (L == 0) ? Aarg : (const float*)d_H0;   // float-A layers
    const unsigned* Ah = (L == 2) ? d_D1h : d_H1h;           // half-A layers
    const float* Wb = (L <= 1) ? (Warg + (size_t)e * KD * ND)
                    : (L == 2) ? (d_W1T + (size_t)e * HID * HID)
                               : (d_W0T + (size_t)e * HID * INDIM);

    float acc[2][8][4];
#pragma unroll
    for (int mt = 0; mt < 2; mt++)
#pragma unroll
        for (int nt = 0; nt < 8; nt++)
#pragma unroll
            for (int j = 0; j < 4; j++) acc[mt][nt][j] = 0.f;

    const int arow  = tid >> 1;
    const int ahalf = tid & 1;

    float4 avA[2];
    uint4 avH;
    float bxv[4], byv[4];
    bool avalid = true;

    // ---- preload chunk 0 ----
    {
        if (AHALF) {
            avH = *(const uint4*)(Ah + (size_t)(row0 + arow) * (KD / 2) + ahalf * 4);
        } else if (L == 0) {
            int g = sPerm[arow];
            avalid = (g >= 0);
            const float* src = A + (size_t)(avalid ? g : 0) * KD + ahalf * 8;
            avA[0] = avalid ? *(const float4*)(src)     : make_float4(0,0,0,0);
            avA[1] = avalid ? *(const float4*)(src + 4) : make_float4(0,0,0,0);
        } else {
            const float* src = A + (size_t)(row0 + arow) * KD + ahalf * 8;
            avA[0] = *(const float4*)(src);
            avA[1] = *(const float4*)(src + 4);
        }
#pragma unroll
        for (int t = 0; t < 4; t++) {
            int idx = tid + t * 256;
            int kp = idx >> 7;
            int n  = idx & 127;
            const float* s = Wb + (size_t)(2 * kp) * ND + ncol0 + n;
            bxv[t] = s[0];
            byv[t] = s[ND];
        }
    }

    for (int k0 = 0; k0 < KD; k0 += 16) {
        __syncthreads();
        // ---- store current chunk ----
        if (AHALF) {
            int kp = ahalf * 4;
            As_hi[arow][kp]     = avH.x;
            As_hi[arow][kp + 1] = avH.y;
            As_hi[arow][kp + 2] = avH.z;
            As_hi[arow][kp + 3] = avH.w;
        } else {
#pragma unroll
            for (int j2 = 0; j2 < 2; j2++) {
                int kp = ahalf * 4 + j2 * 2;
                float4 v = avA[j2];
                if (PASSES == 2) {
                    hsplit_pair(v.x, v.y, As_hi[arow][kp],     As_lo[arow][kp]);
                    hsplit_pair(v.z, v.w, As_hi[arow][kp + 1], As_lo[arow][kp + 1]);
                } else {
                    As_hi[arow][kp]     = hpack(v.x, v.y);
                    As_hi[arow][kp + 1] = hpack(v.z, v.w);
                }
            }
        }
#pragma unroll
        for (int t = 0; t < 4; t++) {
            int idx = tid + t * 256;
            int kp = idx >> 7;
            int n  = idx & 127;
            Bs_hi[kp][n] = hpack(bxv[t], byv[t]);
        }
        __syncthreads();

        // ---- preload next chunk while mma runs ----
        if (k0 + 16 < KD) {
            int kn = k0 + 16;
            if (AHALF) {
                avH = *(const uint4*)(Ah + (size_t)(row0 + arow) * (KD / 2)
                                      + kn / 2 + ahalf * 4);
            } else if (L == 0) {
                const float* src = A + (size_t)(avalid ? sPerm[arow] : 0) * KD
                                   + kn + ahalf * 8;
                avA[0] = avalid ? *(const float4*)(src)     : make_float4(0,0,0,0);
                avA[1] = avalid ? *(const float4*)(src + 4) : make_float4(0,0,0,0);
            } else {
                const float* src = A + (size_t)(row0 + arow) * KD + kn + ahalf * 8;
                avA[0] = *(const float4*)(src);
                avA[1] = *(const float4*)(src + 4);
            }
#pragma unroll
            for (int t = 0; t < 4; t++) {
                int idx = tid + t * 256;
                int kp = idx >> 7;
                int n  = idx & 127;
                const float* s = Wb + (size_t)(kn + 2 * kp) * ND + ncol0 + n;
                bxv[t] = s[0];
                byv[t] = s[ND];
            }
        }

        // ---- fragments + mma ----
        unsigned ah[2][4], al[2][4];
        const int kp = lane & 3;
#pragma unroll
        for (int mt = 0; mt < 2; mt++) {
            int m = wm * 32 + mt * 16 + (lane >> 2);
            ah[mt][0] = As_hi[m][kp];
            ah[mt][1] = As_hi[m + 8][kp];
            ah[mt][2] = As_hi[m][kp + 4];
            ah[mt][3] = As_hi[m + 8][kp + 4];
            if (PASSES == 2) {
                al[mt][0] = As_lo[m][kp];
                al[mt][1] = As_lo[m + 8][kp];
                al[mt][2] = As_lo[m][kp + 4];
                al[mt][3] = As_lo[m + 8][kp + 4];
            }
        }
#pragma unroll
        for (int nt = 0; nt < 8; nt++) {
            int n = wn * 64 + nt * 8 + (lane >> 2);
            unsigned bh0 = Bs_hi[kp][n];
            unsigned bh1 = Bs_hi[kp + 4][n];
#pragma unroll
            for (int mt = 0; mt < 2; mt++) {
                mma16h(acc[mt][nt], ah[mt], bh0, bh1);
                if (PASSES == 2)
                    mma16h(acc[mt][nt], al[mt], bh0, bh1);
            }
        }
    }

    // ---- epilogue ----
    float erow[2][2];
    if (L == 1) {
        erow[0][0] = erow[0][1] = erow[1][0] = erow[1][1] = 0.f;
    }
#pragma unroll
    for (int mt = 0; mt < 2; mt++) {
#pragma unroll
        for (int nt = 0; nt < 8; nt++) {
            float* cc = acc[mt][nt];
            int rloc = wm * 32 + mt * 16 + (lane >> 2);
            int c = ncol0 + wn * 64 + nt * 8 + (lane & 3) * 2;
            if (L == 0) {
                float2 b = *(const float2*)&dp_b0[e * ND + c];
                size_t r0i = (size_t)(row0 + rloc) * ND + c;
                size_t r1i = (size_t)(row0 + rloc + 8) * ND + c;
                d_H0[r0i]     = tanhf(cc[0] + b.x);
                d_H0[r0i + 1] = tanhf(cc[1] + b.y);
                d_H0[r1i]     = tanhf(cc[2] + b.x);
                d_H0[r1i + 1] = tanhf(cc[3] + b.y);
            } else if (L == 1) {
                float2 b = *(const float2*)&dp_b1[e * ND + c];
                float2 w = *(const float2*)&dp_w2[e * ND + c];
                float h0 = tanhf(cc[0] + b.x);
                float h1 = tanhf(cc[1] + b.y);
                float h2 = tanhf(cc[2] + b.x);
                float h3 = tanhf(cc[3] + b.y);
                d_D1h[(size_t)(row0 + rloc) * (ND / 2) + (c >> 1)] =
                    hpack(w.x * (1.f - h0 * h0), w.y * (1.f - h1 * h1));
                d_D1h[(size_t)(row0 + rloc + 8) * (ND / 2) + (c >> 1)] =
                    hpack(w.x * (1.f - h2 * h2), w.y * (1.f - h3 * h3));
                erow[mt][0] += h0 * w.x + h1 * w.y;
                erow[mt][1] += h2 * w.x + h3 * w.y;
            } else if (L == 2) {
                size_t r0i = (size_t)(row0 + rloc) * ND + c;
                size_t r1i = (size_t)(row0 + rloc + 8) * ND + c;
                float2 h0 = *(const float2*)&d_H0[r0i];
                float2 h1 = *(const float2*)&d_H0[r1i];
                d_H1h[(size_t)(row0 + rloc) * (ND / 2) + (c >> 1)] =
                    hpack(cc[0] * (1.f - h0.x * h0.x), cc[1] * (1.f - h0.y * h0.y));
                d_H1h[(size_t)(row0 + rloc + 8) * (ND / 2) + (c >> 1)] =
                    hpack(cc[2] * (1.f - h1.x * h1.x), cc[3] * (1.f - h1.y * h1.y));
            } else {
                int a0 = sPerm[rloc];
                int a1 = sPerm[rloc + 8];
                if (a0 >= 0) {
                    d_G[(size_t)a0 * ND + c]     = cc[0];
                    d_G[(size_t)a0 * ND + c + 1] = cc[1];
                }
                if (a1 >= 0) {
                    d_G[(size_t)a1 * ND + c]     = cc[2];
                    d_G[(size_t)a1 * ND + c + 1] = cc[3];
                }
            }
        }
    }

    if (L == 1) {
        // reduce partial energies, then fused segment-sum (b2 added once at y=0)
#pragma unroll
        for (int mt = 0; mt < 2; mt++)
#pragma unroll
            for (int h = 0; h < 2; h++) {
                float v = erow[mt][h];
                v += __shfl_xor_sync(0xffffffffu, v, 1);
                v += __shfl_xor_sync(0xffffffffu, v, 2);
                if ((lane & 3) == 0) {
                    int rloc = wm * 32 + mt * 16 + (lane >> 2) + h * 8;
                    atomicAdd(&s_row[rloc], v);
                }
            }
        __syncthreads();
        if (tid < 128) {
            int atom = sPerm[tid];
            if (atom >= 0) {
                float v = s_row[tid];
                if (ncol0 == 0) v += Aarg[e];   // Aarg carries b2 for L=1
                atomicAdd(&Carg[ld_idx(dp_img, atom, d_is64[0])], v);
            }
        }
    }
}

// ---------------- sparse transpose scatter (2 nnz per thread) --------------
__global__ void k_sparse(float* __restrict__ out) {
    int i0 = (blockIdx.x * blockDim.x + threadIdx.x) * 2;
    const int is64 = d_is64[1];
    const int* rows = dp_rows;
    const int* cols = dp_cols;
    const float* vals = dp_vals;
#pragma unroll
    for (int j = 0; j < 2; j++) {
        int i = i0 + j;
        if (i < NNZV) {
            float g = d_G[ld_idx(rows, i, is64)];
            atomicAdd(&out[NIMG + ld_idx(cols, i, is64)], -vals[i] * g);
        }
    }
}

// ---------------- launch ----------------
extern "C" void kernel_launch(void* const* d_in, const int* in_sizes, int n_in,
                              void* d_out, int out_size) {
    int i_fp = 0, i_W0 = 6, i_W1 = 8, i_b2 = 11;
    int p50[2] = {1, 2};
    int p2M[3] = {3, 4, 5};
    int p1k[3] = {7, 9, 10};

    {
        int fp = -1, w0 = -1, w1 = -1, b2p = -1;
        int c50[2], n50 = 0, c2M[3], n2M = 0, c1k[3], n1k = 0;
        for (int i = 0; i < n_in; i++) {
            int s = in_sizes[i];
            if (s == 6400000) fp = i;
            else if (s == 131072) w0 = i;
            else if (s == 262144) w1 = i;
            else if (s == 4) b2p = i;
            else if (s == 50000 || s == 100000) { if (n50 < 2) c50[n50++] = i; }
            else if (s == 2000000 || s == 4000000) { if (n2M < 3) c2M[n2M++] = i; }
            else if (s == 1024) { if (n1k < 3) c1k[n1k++] = i; }
        }
        if (fp >= 0 && w0 >= 0 && w1 >= 0 && b2p >= 0 &&
            n50 == 2 && n2M == 3 && n1k == 3) {
            i_fp = fp; i_W0 = w0; i_W1 = w1; i_b2 = b2p;
            p50[0] = c50[0]; p50[1] = c50[1];
            p2M[0] = c2M[0]; p2M[1] = c2M[1]; p2M[2] = c2M[2];
            p1k[0] = c1k[0]; p1k[1] = c1k[1]; p1k[2] = c1k[2];
        }
    }

    const float* fp = (const float*)d_in[i_fp];
    const float* W0 = (const float*)d_in[i_W0];
    const float* W1 = (const float*)d_in[i_W1];
    const float* b2 = (const float*)d_in[i_b2];
    float* out = (float*)d_out;
    (void)out_size;

    k_detect<<<1, 256>>>((const int*)d_in[p50[0]], (const int*)d_in[p50[1]],
                         (const int*)d_in[p2M[0]], (const int*)d_in[p2M[1]],
                         (const int*)d_in[p2M[2]],
                         (const float*)d_in[p1k[0]], (const float*)d_in[p1k[1]],
                         (const float*)d_in[p1k[2]]);
    k_prep<<<(OUTSZ + 255) / 256, 256>>>(out);
    k_scatter<<<(NATOMS + 255) / 256, 256>>>();
    {
        int ntr = NELEM * HID * INDIM + NELEM * HID * HID;
        k_transpose<<<(ntr + 255) / 256, 256>>>(W0, W1);
    }

    dim3 gfull(NT128, 2);   // ND=256
    dim3 ghalf(NT128, 1);   // ND=128

    k_gemm_tc<0, 2><<<gfull, 256>>>(fp, W0, nullptr);       // H0 (fp16 2-pass)
    k_gemm_tc<1, 2><<<gfull, 256>>>(b2, W1, out);           // D1h + energy (fused)
    k_gemm_tc<2, 1><<<gfull, 256>>>(nullptr, nullptr, nullptr); // D0h (fp16 1-pass)
    k_gemm_tc<3, 1><<<ghalf, 256>>>(nullptr, nullptr, nullptr); // G scatter
    k_sparse<<<(NNZV / 2 + 255) / 256, 256>>>(out);         // forces
}